// round 2
// baseline (speedup 1.0000x reference)
#include <cuda_runtime.h>

#define G     8
#define KS    7
#define KK    49            // KS*KS
#define GP    392           // G*KK
#define COUT  128
#define CIN   128
#define CTILE 8             // cin per block
#define NBLK  (COUT * (CIN / CTILE))   // 2048

// ---- precomputed tables (setup kernel -> main kernel) ----
__device__ int4   g_toff[GP];   // per (o,pos): 4 bilinear tap offsets into a 49-float plane
__device__ float4 g_tw[GP];     // per (o,pos): 4 tap weights (circular mask folded in)
__device__ float  g_hA[64];     // per (o,g): coeff for B[g]
__device__ float  g_hB[64];     // per (o,g): coeff for B[(g+1)&7]
__device__ int    g_hOff[64];   // per (o,g): i*49 (output i-slot for this g)

__global__ void setup_kernel(const float* __restrict__ in_H,
                             const float* __restrict__ out_H,
                             const float* __restrict__ grid_Rn,
                             const float* __restrict__ mask)
{
    const float TP = 6.283185307179586f;   // f32(2*pi)
    const float C8 = 0.7853981633974483f;  // f32(2*pi/8)
    int tid = threadIdx.x;

    if (tid < GP) {
        // bilinear tap table: depends only on o (rotation) and pos
        int o = tid / KK, p = tid % KK;
        float oi = -out_H[o];
        float c = cosf(oi), s = sinf(oi);
        float x = grid_Rn[2 * p + 0], y = grid_Rn[2 * p + 1];
        float rx = c * x - s * y;
        float ry = s * x + c * y;
        float px = (rx + 1.0f) * 0.5f * (float)(KS - 1);
        float py = (ry + 1.0f) * 0.5f * (float)(KS - 1);
        float x0 = floorf(px), y0 = floorf(py);
        float wx = px - x0, wy = py - y0;
        float m = mask[p];
        int ix0 = (int)x0, iy0 = (int)y0;

        int   xs[4] = { ix0, ix0 + 1, ix0,     ix0 + 1 };
        int   ys[4] = { iy0, iy0,     iy0 + 1, iy0 + 1 };
        float ws[4] = { (1.0f - wx) * (1.0f - wy), wx * (1.0f - wy),
                        (1.0f - wx) * wy,          wx * wy };
        int offs[4]; float wout[4];
        #pragma unroll
        for (int t = 0; t < 4; ++t) {
            bool inb = (xs[t] >= 0) && (xs[t] <= KS - 1) &&
                       (ys[t] >= 0) && (ys[t] <= KS - 1);
            int xc = min(max(xs[t], 0), KS - 1);
            int yc = min(max(ys[t], 0), KS - 1);
            offs[t] = yc * KS + xc;
            wout[t] = inb ? ws[t] * m : 0.0f;
        }
        g_toff[tid] = make_int4(offs[0], offs[1], offs[2], offs[3]);
        g_tw[tid]   = make_float4(wout[0], wout[1], wout[2], wout[3]);
    } else if (tid < GP + 64) {
        // H-lerp table, keyed by g = nominal (i-o) mod 8 (bijective per o,
        // so every (o,k) slot below is written exactly once per launch)
        int t = tid - GP;
        int o = t >> 3, i = t & 7;
        float q = in_H[i] - out_H[o];
        float r = fmodf(q, TP);
        if (r < 0.0f) r += TP;          // jnp.mod semantics (result in [0, 2pi))
        float pos = r / C8;             // in [0, 8)
        int k = (i - o + 8) & 7;        // nominal integer base
        float wv = pos - (float)k;      // tiny fp32 residual (|wv| ~ 1e-6)
        g_hA[o * 8 + k]   = 1.0f - wv;
        g_hB[o * 8 + k]   = wv;
        g_hOff[o * 8 + k] = i * KK;
    }
}

__global__ void __launch_bounds__(392)
main_kernel(const float* __restrict__ W, float* __restrict__ out)
{
    __shared__ float tile[CTILE * GP];          // 8 cin x 392 floats = 12.5 KB

    int cout = blockIdx.x >> 4;
    int cin0 = (blockIdx.x & 15) << 3;
    int tid  = threadIdx.y * KK + threadIdx.x;  // 0..391

    // stage weight[cout, cin0..cin0+7, :, :, :] (contiguous 3136 floats) via float4
    const float4* Wg = reinterpret_cast<const float4*>(W) +
                       (size_t)(cout * CIN + cin0) * (GP / 4);
    float4* t4 = reinterpret_cast<float4*>(tile);
    t4[tid]       = __ldg(Wg + tid);
    t4[tid + 392] = __ldg(Wg + tid + 392);
    __syncthreads();

    int pos = threadIdx.x;                       // 0..48
    const float* tc = tile + threadIdx.y * GP;   // this thread's cin plane-set
    int cin    = cin0 + threadIdx.y;
    int ccbase = (cout * G) * CIN + cin;         // (cout*8 + o)*128 + cin, o added below

    #pragma unroll 1
    for (int o = 0; o < G; ++o) {
        int4   toff = __ldg(&g_toff[o * KK + pos]);
        float4 tw   = __ldg(&g_tw[o * KK + pos]);

        // B[g] = bilinear-rotated sample of weight plane g at this pos
        float B[8];
        #pragma unroll
        for (int g = 0; g < 8; ++g) {
            const float* tp = tc + g * KK;
            B[g] = tw.x * tp[toff.x] + tw.y * tp[toff.y]
                 + tw.z * tp[toff.z] + tw.w * tp[toff.w];
        }

        int base = ((ccbase + o * CIN) * G) * KK + pos;
        #pragma unroll
        for (int g = 0; g < 8; ++g) {
            float a  = __ldg(&g_hA[o * 8 + g]);
            float b  = __ldg(&g_hB[o * 8 + g]);
            int   io = __ldg(&g_hOff[o * 8 + g]);   // warp-uniform -> coalesced store
            float v  = a * B[g] + b * B[(g + 1) & 7];
            __stcs(&out[base + io], v);             // streaming store, spare L2 for weights
        }
    }
}

extern "C" void kernel_launch(void* const* d_in, const int* in_sizes, int n_in,
                              void* d_out, int out_size)
{
    const float* W      = (const float*)d_in[0];  // weight [128,128,8,7,7]
    const float* inH    = (const float*)d_in[1];  // in_H [8]
    const float* outH   = (const float*)d_in[2];  // out_H [8]
    // d_in[3] = grid_H (unused; == in_H)
    const float* gridRn = (const float*)d_in[4];  // grid_Rn [7,7,2]
    const float* maskp  = (const float*)d_in[5];  // mask [7,7]

    setup_kernel<<<1, 456>>>(inH, outH, gridRn, maskp);

    dim3 blk(KK, CTILE);                          // (49, 8) = 392 threads
    main_kernel<<<NBLK, blk>>>(W, (float*)d_out);
}

// round 3
// speedup vs baseline: 1.2589x; 1.2589x over previous
#include <cuda_runtime.h>

#define G     8
#define KS    7
#define KK    49            // KS*KS
#define GP    392           // G*KK
#define COUT  128
#define CIN   128
#define CTILE 8             // cin per block
#define NBLK  (COUT * (CIN / CTILE))   // 2048

// ---- precomputed tables (setup kernel -> main kernel) ----
__device__ int4   g_toff[GP];   // per (o,pos): 4 bilinear tap offsets (odd o path)
__device__ float4 g_tw[GP];     // per (o,pos): 4 tap weights, mask folded in
__device__ int    g_soff[GP];   // per (o,pos): argmax tap offset (even o path)
__device__ float  g_sw[GP];     // per (o,pos): total weight on argmax tap
__device__ float  g_hA[64];     // per (o,g): coeff for B[g]
__device__ float  g_hB[64];     // per (o,g): coeff for B[(g+1)&7]
__device__ int    g_hOff[64];   // per (o,g): i*49 (output i-slot for this g)

__global__ void setup_kernel(const float* __restrict__ in_H,
                             const float* __restrict__ out_H,
                             const float* __restrict__ grid_Rn,
                             const float* __restrict__ mask)
{
    const float TP = 6.283185307179586f;   // f32(2*pi)
    const float C8 = 0.7853981633974483f;  // f32(2*pi/8)
    int tid = threadIdx.x;

    if (tid < GP) {
        int o = tid / KK, p = tid % KK;
        float oi = -out_H[o];
        float c = cosf(oi), s = sinf(oi);
        float x = grid_Rn[2 * p + 0], y = grid_Rn[2 * p + 1];
        float rx = c * x - s * y;
        float ry = s * x + c * y;
        float px = (rx + 1.0f) * 0.5f * (float)(KS - 1);
        float py = (ry + 1.0f) * 0.5f * (float)(KS - 1);
        float x0 = floorf(px), y0 = floorf(py);
        float wx = px - x0, wy = py - y0;
        float m = mask[p];
        int ix0 = (int)x0, iy0 = (int)y0;

        int   xs[4] = { ix0, ix0 + 1, ix0,     ix0 + 1 };
        int   ys[4] = { iy0, iy0,     iy0 + 1, iy0 + 1 };
        float ws[4] = { (1.0f - wx) * (1.0f - wy), wx * (1.0f - wy),
                        (1.0f - wx) * wy,          wx * wy };
        int offs[4]; float wout[4];
        #pragma unroll
        for (int t = 0; t < 4; ++t) {
            bool inb = (xs[t] >= 0) && (xs[t] <= KS - 1) &&
                       (ys[t] >= 0) && (ys[t] <= KS - 1);
            int xc = min(max(xs[t], 0), KS - 1);
            int yc = min(max(ys[t], 0), KS - 1);
            offs[t] = yc * KS + xc;
            wout[t] = inb ? ws[t] * m : 0.0f;
        }
        g_toff[tid] = make_int4(offs[0], offs[1], offs[2], offs[3]);
        g_tw[tid]   = make_float4(wout[0], wout[1], wout[2], wout[3]);

        // compact single-tap form (used for even o, where the rotation is
        // lattice-exact and >1-1e-6 of the weight sits on one tap)
        int   bi = 0;
        float bw = wout[0];
        #pragma unroll
        for (int t = 1; t < 4; ++t)
            if (wout[t] > bw) { bw = wout[t]; bi = t; }
        g_soff[tid] = offs[bi];
        g_sw[tid]   = wout[0] + wout[1] + wout[2] + wout[3];
    } else if (tid < GP + 64) {
        // H-lerp table, keyed by g = nominal (i-o) mod 8 (bijective per o)
        int t = tid - GP;
        int o = t >> 3, i = t & 7;
        float q = in_H[i] - out_H[o];
        float r = fmodf(q, TP);
        if (r < 0.0f) r += TP;          // jnp.mod semantics (result in [0, 2pi))
        float pos = r / C8;             // in [0, 8)
        int k = (i - o + 8) & 7;        // nominal integer base
        float wv = pos - (float)k;      // tiny fp32 residual (|wv| ~ 1e-6)
        g_hA[o * 8 + k]   = 1.0f - wv;
        g_hB[o * 8 + k]   = wv;
        g_hOff[o * 8 + k] = i * KK;
    }
}

__device__ __forceinline__ void emit_outputs(float* __restrict__ out, int base,
                                             int o, const float B[8])
{
    #pragma unroll
    for (int g = 0; g < 8; ++g) {
        float a  = __ldg(&g_hA[o * 8 + g]);
        float b  = __ldg(&g_hB[o * 8 + g]);
        int   io = __ldg(&g_hOff[o * 8 + g]);   // warp-uniform -> coalesced store
        float v  = a * B[g] + b * B[(g + 1) & 7];
        __stcs(&out[base + io], v);             // streaming store, spare L2
    }
}

__global__ void __launch_bounds__(392)
main_kernel(const float* __restrict__ W, float* __restrict__ out)
{
    __shared__ float tile[CTILE * GP];          // 8 cin x 392 floats = 12.5 KB

    int cout = blockIdx.x >> 4;
    int cin0 = (blockIdx.x & 15) << 3;
    int tid  = threadIdx.y * KK + threadIdx.x;  // 0..391

    // stage weight[cout, cin0..cin0+7, :, :, :] (contiguous 3136 floats) via float4
    const float4* Wg = reinterpret_cast<const float4*>(W) +
                       (size_t)(cout * CIN + cin0) * (GP / 4);
    float4* t4 = reinterpret_cast<float4*>(tile);
    t4[tid]       = __ldg(Wg + tid);
    t4[tid + 392] = __ldg(Wg + tid + 392);
    __syncthreads();

    int pos = threadIdx.x;                       // 0..48
    const float* tc = tile + threadIdx.y * GP;   // this thread's cin plane-set
    int cin    = cin0 + threadIdx.y;
    int ccbase = (cout * G) * CIN + cin;

    #pragma unroll 1
    for (int o = 0; o < G; o += 2) {
        // ---- even o: lattice-exact rotation, single tap ----
        {
            int   so = __ldg(&g_soff[o * KK + pos]);
            float sw = __ldg(&g_sw[o * KK + pos]);
            float B[8];
            #pragma unroll
            for (int g = 0; g < 8; ++g)
                B[g] = sw * tc[g * KK + so];
            int base = ((ccbase + o * CIN) * G) * KK + pos;
            emit_outputs(out, base, o, B);
        }
        // ---- odd o: full 4-tap bilinear ----
        {
            int   o1   = o + 1;
            int4   toff = __ldg(&g_toff[o1 * KK + pos]);
            float4 tw   = __ldg(&g_tw[o1 * KK + pos]);
            float B[8];
            #pragma unroll
            for (int g = 0; g < 8; ++g) {
                const float* tp = tc + g * KK;
                B[g] = tw.x * tp[toff.x] + tw.y * tp[toff.y]
                     + tw.z * tp[toff.z] + tw.w * tp[toff.w];
            }
            int base = ((ccbase + o1 * CIN) * G) * KK + pos;
            emit_outputs(out, base, o1, B);
        }
    }
}

extern "C" void kernel_launch(void* const* d_in, const int* in_sizes, int n_in,
                              void* d_out, int out_size)
{
    const float* W      = (const float*)d_in[0];  // weight [128,128,8,7,7]
    const float* inH    = (const float*)d_in[1];  // in_H [8]
    const float* outH   = (const float*)d_in[2];  // out_H [8]
    // d_in[3] = grid_H (unused; == in_H)
    const float* gridRn = (const float*)d_in[4];  // grid_Rn [7,7,2]
    const float* maskp  = (const float*)d_in[5];  // mask [7,7]

    setup_kernel<<<1, 456>>>(inH, outH, gridRn, maskp);

    dim3 blk(KK, CTILE);                          // (49, 8) = 392 threads
    main_kernel<<<NBLK, blk>>>(W, (float*)d_out);
}